// round 4
// baseline (speedup 1.0000x reference)
#include <cuda_runtime.h>
#include <cuda_bf16.h>
#include <math_constants.h>
#include <limits.h>

// Segment-max pooling with sorted segment ids (N rows x 32 ch -> M segments).
// One warp owns CHUNK=128 consecutive rows; lane = channel.
// Boundary rows are precomputed as a 128-bit ballot mask; the inner loop is
// LDG-batched (BATCH=8, keeps regs ~32 and occupancy ~92%) and checks one
// uniform mask byte per batch. Responsible warp (segment's first row in its
// chunk) extends past chunk end via ballot-scanned id blocks; gaps -> 0.

#define CHUNK 128
#define BATCH 8

typedef unsigned long long ull;

__global__ __launch_bounds__(256) void seg_max_kernel(
    const float* __restrict__ feat,
    const int*   __restrict__ ids,
    float*       __restrict__ out,
    int N, int M)
{
    const unsigned FULL = 0xFFFFFFFFu;
    const int lane = threadIdx.x & 31;
    const int warp = blockIdx.x * (blockDim.x >> 5) + (threadIdx.x >> 5);

    const long long r0 = (long long)warp * CHUNK;
    if (r0 >= N) return;
    const int nrows = (int)(((long long)N - r0 < CHUNK) ? (N - r0) : CHUNK);

    // Coalesced load of this chunk's segment ids (4 x 32 lanes).
    int idr0 = (lane < nrows)       ? ids[r0 + lane]       : 0;
    int idr1 = (32  + lane < nrows) ? ids[r0 + 32  + lane] : 0;
    int idr2 = (64  + lane < nrows) ? ids[r0 + 64  + lane] : 0;
    int idr3 = (96  + lane < nrows) ? ids[r0 + 96  + lane] : 0;

    const int prev_id = (r0 > 0) ? ids[r0 - 1] : -1;

    int   cur  = prev_id;
    bool  resp = false;
    float m    = -CUDART_INF_F;

    const float* fptr = feat + r0 * 32 + lane;

    if (nrows == CHUNK) {
        // 128-bit boundary mask: bit i set iff ids[r0+i] != ids[r0+i-1].
        unsigned mk0, mk1, mk2, mk3;
        {
            int p, s;
            p = __shfl_up_sync(FULL, idr0, 1); if (lane == 0) p = prev_id;
            mk0 = __ballot_sync(FULL, idr0 != p);
            s = __shfl_sync(FULL, idr0, 31);
            p = __shfl_up_sync(FULL, idr1, 1); if (lane == 0) p = s;
            mk1 = __ballot_sync(FULL, idr1 != p);
            s = __shfl_sync(FULL, idr1, 31);
            p = __shfl_up_sync(FULL, idr2, 1); if (lane == 0) p = s;
            mk2 = __ballot_sync(FULL, idr2 != p);
            s = __shfl_sync(FULL, idr2, 31);
            p = __shfl_up_sync(FULL, idr3, 1); if (lane == 0) p = s;
            mk3 = __ballot_sync(FULL, idr3 != p);
        }
        const ull bm0 = (ull)mk0 | ((ull)mk1 << 32);
        const ull bm1 = (ull)mk2 | ((ull)mk3 << 32);

        #pragma unroll
        for (int half = 0; half < 2; ++half) {
            const ull bm = half ? bm1 : bm0;
            #pragma unroll
            for (int base = 0; base < 64; base += BATCH) {
                float v[BATCH];
                #pragma unroll
                for (int j = 0; j < BATCH; ++j)
                    v[j] = fptr[(half * 64 + base + j) * 32];

                const unsigned bb = (unsigned)(bm >> base) & 0xFFu;
                if (bb == 0u) {                      // warp-uniform fast path
                    #pragma unroll
                    for (int j = 0; j < BATCH; ++j)
                        m = fmaxf(m, v[j]);
                } else {
                    #pragma unroll
                    for (int j = 0; j < BATCH; ++j) {
                        if ((bb >> j) & 1u) {        // warp-uniform
                            const int i = half * 64 + base + j;
                            int sel = (i < 32) ? idr0 : (i < 64) ? idr1
                                    : (i < 96) ? idr2 : idr3;
                            int nid = __shfl_sync(FULL, sel, i & 31);
                            if (resp) {
                                out[(long long)cur * 32 + lane] = m;
                                for (int g = cur + 1; g < nid; ++g)
                                    out[(long long)g * 32 + lane] = 0.0f;
                            }
                            cur  = nid;
                            m    = -CUDART_INF_F;
                            resp = true;
                        }
                        m = fmaxf(m, v[j]);
                    }
                }
            }
        }
    } else {
        // Ragged last chunk: scalar path (one warp in the grid).
        for (int i = 0; i < nrows; ++i) {
            int sel = (i < 32) ? idr0 : (i < 64) ? idr1
                    : (i < 96) ? idr2 : idr3;
            int id = __shfl_sync(FULL, sel, i & 31);
            if (id != cur) {
                if (resp) {
                    out[(long long)cur * 32 + lane] = m;
                    for (int g = cur + 1; g < id; ++g)
                        out[(long long)g * 32 + lane] = 0.0f;
                }
                cur  = id;
                m    = -CUDART_INF_F;
                resp = true;
            }
            m = fmaxf(m, fptr[(long long)i * 32]);
        }
    }

    // Finish the last segment we own: it may continue past the chunk end.
    long long r = r0 + nrows;
    if (resp) {
        while (r < N) {                       // uniform condition
            long long rl = r + lane;
            int idn = (rl < N) ? ids[rl] : (cur + 1);   // sentinel != cur
            unsigned diff = __ballot_sync(FULL, idn != cur);
            int k = diff ? (__ffs(diff) - 1) : 32;      // continuation rows
            for (int j = 0; j < k; ++j)                 // independent loads
                m = fmaxf(m, feat[(r + j) * 32 + lane]);
            r += k;
            if (k < 32) break;
        }
        out[(long long)cur * 32 + lane] = m;
        int next_id = (r < N) ? ids[r] : M;
        for (int g = cur + 1; g < next_id; ++g)
            out[(long long)g * 32 + lane] = 0.0f;
    }

    // Leading gap: segments before ids[0] are empty.
    if (r0 == 0) {
        int first = ids[0];
        for (int g = 0; g < first; ++g)
            out[(long long)g * 32 + lane] = 0.0f;
    }
}

extern "C" void kernel_launch(void* const* d_in, const int* in_sizes, int n_in,
                              void* d_out, int out_size) {
    const float* feat = (const float*)d_in[0];
    const int*   ids  = (const int*)d_in[1];
    float*       out  = (float*)d_out;

    const int N = in_sizes[1];
    const int M = out_size / 32;

    const int warps   = (N + CHUNK - 1) / CHUNK;
    const int threads = 256;
    const int blocks  = (warps * 32 + threads - 1) / threads;

    seg_max_kernel<<<blocks, threads>>>(feat, ids, out, N, M);
}

// round 5
// speedup vs baseline: 1.4197x; 1.4197x over previous
#include <cuda_runtime.h>
#include <cuda_bf16.h>
#include <math_constants.h>
#include <limits.h>

// Segment-max pooling with sorted segment ids (N rows x 32 ch -> M segments).
// One warp owns CHUNK=64 consecutive rows; lane = channel.
// Boundary rows are precomputed as a 64-bit ballot mask (2 shfl_up + 2 ballot
// per chunk); the inner loop is LDG-batched (BATCH=8) and checks one uniform
// mask byte per batch -- shfl only at actual flushes (~8/chunk).
// __launch_bounds__(256, 8) pins regs to 32 so occupancy stays ~92%.
// Responsible warp (segment's first row in its chunk) extends past chunk end
// via ballot-scanned id blocks; gaps between ids are empty segments -> 0.

#define CHUNK 64
#define BATCH 8

typedef unsigned long long ull;

__global__ __launch_bounds__(256, 8) void seg_max_kernel(
    const float* __restrict__ feat,
    const int*   __restrict__ ids,
    float*       __restrict__ out,
    int N, int M)
{
    const unsigned FULL = 0xFFFFFFFFu;
    const int lane = threadIdx.x & 31;
    const int warp = blockIdx.x * (blockDim.x >> 5) + (threadIdx.x >> 5);

    const long long r0 = (long long)warp * CHUNK;
    if (r0 >= N) return;
    const int nrows = (int)(((long long)N - r0 < CHUNK) ? (N - r0) : CHUNK);

    // Coalesced load of this chunk's segment ids (2 x 32 lanes).
    int id_lo = (lane < nrows)      ? ids[r0 + lane]      : 0;
    int id_hi = (32 + lane < nrows) ? ids[r0 + 32 + lane] : 0;

    const int prev_id = (r0 > 0) ? ids[r0 - 1] : -1;

    int   cur  = prev_id;
    bool  resp = false;
    float m    = -CUDART_INF_F;

    const float* fptr = feat + r0 * 32 + lane;

    if (nrows == CHUNK) {
        // 64-bit boundary mask: bit i set iff ids[r0+i] != ids[r0+i-1].
        int p = __shfl_up_sync(FULL, id_lo, 1);
        if (lane == 0) p = prev_id;
        unsigned mlo = __ballot_sync(FULL, id_lo != p);

        int s = __shfl_sync(FULL, id_lo, 31);
        p = __shfl_up_sync(FULL, id_hi, 1);
        if (lane == 0) p = s;
        unsigned mhi = __ballot_sync(FULL, id_hi != p);

        const ull bmask = (ull)mlo | ((ull)mhi << 32);

        #pragma unroll
        for (int base = 0; base < CHUNK; base += BATCH) {
            float v[BATCH];
            #pragma unroll
            for (int j = 0; j < BATCH; ++j)
                v[j] = fptr[(base + j) * 32];

            const unsigned bb = (unsigned)(bmask >> base) & 0xFFu;
            if (bb == 0u) {                       // warp-uniform fast path
                #pragma unroll
                for (int j = 0; j < BATCH; ++j)
                    m = fmaxf(m, v[j]);
            } else {
                #pragma unroll
                for (int j = 0; j < BATCH; ++j) {
                    if ((bb >> j) & 1u) {         // warp-uniform (mask)
                        const int i = base + j;
                        int nid = __shfl_sync(FULL, (i < 32) ? id_lo : id_hi,
                                              i & 31);
                        if (resp) {
                            out[(long long)cur * 32 + lane] = m;
                            for (int g = cur + 1; g < nid; ++g)
                                out[(long long)g * 32 + lane] = 0.0f;
                        }
                        cur  = nid;
                        m    = -CUDART_INF_F;
                        resp = true;
                    }
                    m = fmaxf(m, v[j]);
                }
            }
        }
    } else {
        // Ragged last chunk: scalar path (one warp in the grid).
        for (int i = 0; i < nrows; ++i) {
            int id = __shfl_sync(FULL, (i < 32) ? id_lo : id_hi, i & 31);
            if (id != cur) {
                if (resp) {
                    out[(long long)cur * 32 + lane] = m;
                    for (int g = cur + 1; g < id; ++g)
                        out[(long long)g * 32 + lane] = 0.0f;
                }
                cur  = id;
                m    = -CUDART_INF_F;
                resp = true;
            }
            m = fmaxf(m, fptr[(long long)i * 32]);
        }
    }

    // Finish the last segment we own: it may continue past the chunk end.
    long long r = r0 + nrows;
    if (resp) {
        while (r < N) {                       // uniform condition
            long long rl = r + lane;
            int idn = (rl < N) ? ids[rl] : (cur + 1);   // sentinel != cur
            unsigned diff = __ballot_sync(FULL, idn != cur);
            int k = diff ? (__ffs(diff) - 1) : 32;      // continuation rows
            for (int j = 0; j < k; ++j)                 // independent loads
                m = fmaxf(m, feat[(r + j) * 32 + lane]);
            r += k;
            if (k < 32) break;
        }
        out[(long long)cur * 32 + lane] = m;
        int next_id = (r < N) ? ids[r] : M;
        for (int g = cur + 1; g < next_id; ++g)
            out[(long long)g * 32 + lane] = 0.0f;
    }

    // Leading gap: segments before ids[0] are empty.
    if (r0 == 0) {
        int first = ids[0];
        for (int g = 0; g < first; ++g)
            out[(long long)g * 32 + lane] = 0.0f;
    }
}

extern "C" void kernel_launch(void* const* d_in, const int* in_sizes, int n_in,
                              void* d_out, int out_size) {
    const float* feat = (const float*)d_in[0];
    const int*   ids  = (const int*)d_in[1];
    float*       out  = (float*)d_out;

    const int N = in_sizes[1];
    const int M = out_size / 32;

    const int warps   = (N + CHUNK - 1) / CHUNK;
    const int threads = 256;
    const int blocks  = (warps * 32 + threads - 1) / threads;

    seg_max_kernel<<<blocks, threads>>>(feat, ids, out, N, M);
}

// round 6
// speedup vs baseline: 1.4734x; 1.0379x over previous
#include <cuda_runtime.h>
#include <cuda_bf16.h>
#include <math_constants.h>
#include <limits.h>

// Segment-max pooling with sorted segment ids (N rows x 32 ch -> M segments).
// One warp owns CHUNK=64 rows; lane = channel. Boundary rows precomputed as a
// 64-bit ballot mask. Skip-start: rows before the warp's first boundary belong
// to a segment owned by an earlier warp -- their loads are skipped entirely,
// eliminating all duplicate feat traffic. Tail ids are prefetched at kernel
// start to cut one serial DRAM round trip. regs pinned via launch_bounds.

#define CHUNK 64
#define BATCH 8

typedef unsigned long long ull;

__global__ __launch_bounds__(256, 8) void seg_max_kernel(
    const float* __restrict__ feat,
    const int*   __restrict__ ids,
    float*       __restrict__ out,
    int N, int M)
{
    const unsigned FULL = 0xFFFFFFFFu;
    const int lane = threadIdx.x & 31;
    const int warp = blockIdx.x * (blockDim.x >> 5) + (threadIdx.x >> 5);

    const long long r0 = (long long)warp * CHUNK;
    if (r0 >= N) return;
    const int nrows = (int)(((long long)N - r0 < CHUNK) ? (N - r0) : CHUNK);

    // Coalesced load of this chunk's segment ids (2 x 32 lanes).
    int id_lo = (lane < nrows)      ? ids[r0 + lane]      : 0;
    int id_hi = (32 + lane < nrows) ? ids[r0 + 32 + lane] : 0;
    // Prefetch the 32 ids after the chunk (tail scan input), issued early.
    int idn0  = (r0 + CHUNK + lane < N) ? ids[r0 + CHUNK + lane] : INT_MAX;

    const int prev_id = (r0 > 0) ? ids[r0 - 1] : -1;

    int   cur  = prev_id;
    bool  resp = false;
    float m    = -CUDART_INF_F;

    const float* fptr = feat + r0 * 32 + lane;

    if (nrows == CHUNK) {
        // 64-bit boundary mask: bit i set iff ids[r0+i] != ids[r0+i-1].
        int p = __shfl_up_sync(FULL, id_lo, 1);
        if (lane == 0) p = prev_id;
        unsigned mlo = __ballot_sync(FULL, id_lo != p);

        int s = __shfl_sync(FULL, id_lo, 31);
        p = __shfl_up_sync(FULL, id_hi, 1);
        if (lane == 0) p = s;
        unsigned mhi = __ballot_sync(FULL, id_hi != p);

        const ull bmask = (ull)mlo | ((ull)mhi << 32);
        // First row we own: rows before i0 continue an earlier warp's segment
        // and are read by that warp's tail scan -- skip their loads entirely.
        const int i0 = bmask ? (__ffsll((long long)bmask) - 1) : CHUNK;

        #pragma unroll
        for (int base = 0; base < CHUNK; base += BATCH) {
            if (base + BATCH <= i0) continue;     // warp-uniform full skip

            float v[BATCH];
            #pragma unroll
            for (int j = 0; j < BATCH; ++j)
                v[j] = (base + j >= i0) ? __ldcs(&fptr[(base + j) * 32])
                                        : -CUDART_INF_F;

            const unsigned bb = (unsigned)(bmask >> base) & 0xFFu;
            if (bb == 0u) {                       // warp-uniform fast path
                #pragma unroll
                for (int j = 0; j < BATCH; ++j)
                    m = fmaxf(m, v[j]);
            } else {
                #pragma unroll
                for (int j = 0; j < BATCH; ++j) {
                    if ((bb >> j) & 1u) {         // warp-uniform (mask)
                        const int i = base + j;
                        int nid = __shfl_sync(FULL, (i < 32) ? id_lo : id_hi,
                                              i & 31);
                        if (resp) {
                            out[(long long)cur * 32 + lane] = m;
                            for (int g = cur + 1; g < nid; ++g)
                                out[(long long)g * 32 + lane] = 0.0f;
                        }
                        cur  = nid;
                        m    = -CUDART_INF_F;
                        resp = true;
                    }
                    m = fmaxf(m, v[j]);
                }
            }
        }
    } else {
        // Ragged last chunk: scalar path (one warp in the grid).
        for (int i = 0; i < nrows; ++i) {
            int id = __shfl_sync(FULL, (i < 32) ? id_lo : id_hi, i & 31);
            if (id != cur) {
                if (resp) {
                    out[(long long)cur * 32 + lane] = m;
                    for (int g = cur + 1; g < id; ++g)
                        out[(long long)g * 32 + lane] = 0.0f;
                }
                cur  = id;
                m    = -CUDART_INF_F;
                resp = true;
            }
            m = fmaxf(m, fptr[(long long)i * 32]);
        }
    }

    // Finish the last segment we own: it may continue past the chunk end.
    long long r = r0 + nrows;
    if (resp) {
        bool first = (nrows == CHUNK);
        while (r < N) {                       // uniform condition
            long long rl = r + lane;
            int idn = first ? idn0
                            : ((rl < N) ? ids[rl] : INT_MAX);
            first = false;
            unsigned diff = __ballot_sync(FULL, idn != cur);
            int k = diff ? (__ffs(diff) - 1) : 32;      // continuation rows
            for (int j = 0; j < k; ++j)                 // independent loads
                m = fmaxf(m, __ldcs(&feat[(r + j) * 32 + lane]));
            r += k;
            if (k < 32) break;
        }
        out[(long long)cur * 32 + lane] = m;
        int next_id = (r < N) ? ids[r] : M;
        for (int g = cur + 1; g < next_id; ++g)
            out[(long long)g * 32 + lane] = 0.0f;
    }

    // Leading gap: segments before ids[0] are empty.
    if (r0 == 0) {
        int first_id = ids[0];
        for (int g = 0; g < first_id; ++g)
            out[(long long)g * 32 + lane] = 0.0f;
    }
}

extern "C" void kernel_launch(void* const* d_in, const int* in_sizes, int n_in,
                              void* d_out, int out_size) {
    const float* feat = (const float*)d_in[0];
    const int*   ids  = (const int*)d_in[1];
    float*       out  = (float*)d_out;

    const int N = in_sizes[1];
    const int M = out_size / 32;

    const int warps   = (N + CHUNK - 1) / CHUNK;
    const int threads = 256;
    const int blocks  = (warps * 32 + threads - 1) / threads;

    seg_max_kernel<<<blocks, threads>>>(feat, ids, out, N, M);
}